// round 3
// baseline (speedup 1.0000x reference)
#include <cuda_runtime.h>
#include <cuda_bf16.h>

// HyperedgeMeanAggregator: out[h, :] = mean over entries e with seg_ids[e]==h of
// embed_table[node_idx[e], :].  seg_ids is SORTED.
//
// NOTE: JAX default config has x64 disabled, so node_idx/seg_ids arrive as
// int32 despite the reference saying int64.
//
// Inputs (metadata order):
//   d_in[0] = embed_table  float32 [200000*128]
//   d_in[1] = node_idx     int32   [1600000]
//   d_in[2] = seg_ids      int32   [1600000]  (sorted)
//   d_in[3] = num_hyperedges (scalar, unused; H derived from out_size)
// Output: float32 [H*128]

#define FEAT 128
#define FEAT4 (FEAT / 4)          // 32 float4 per row -> one warp covers a row
#define CHUNK 128                 // entries per warp
#define AGG_BLOCK 256             // 8 warps per block
#define MAX_H 65536

__device__ float g_counts[MAX_H];

__global__ void zero_kernel(float* __restrict__ out, int out_vec4, int H) {
    int stride = gridDim.x * blockDim.x;
    int i = blockIdx.x * blockDim.x + threadIdx.x;
    float4 z = make_float4(0.f, 0.f, 0.f, 0.f);
    for (int j = i; j < out_vec4; j += stride)
        reinterpret_cast<float4*>(out)[j] = z;
    for (int j = i; j < H; j += stride)
        g_counts[j] = 0.f;
}

__global__ void agg_kernel(const float* __restrict__ table,
                           const int* __restrict__ node_idx,
                           const int* __restrict__ seg_ids,
                           float* __restrict__ out,
                           int E) {
    int gwarp = (blockIdx.x * blockDim.x + threadIdx.x) >> 5;
    int lane  = threadIdx.x & 31;

    int start = gwarp * CHUNK;
    if (start >= E) return;
    int end = start + CHUNK;
    if (end > E) end = E;

    const float4* t4 = reinterpret_cast<const float4*>(table);

    float4 acc = make_float4(0.f, 0.f, 0.f, 0.f);
    float  cnt = 0.f;
    int cur = __ldg(&seg_ids[start]);

    for (int e = start; e < end; ++e) {
        int s = __ldg(&seg_ids[e]);
        int n = __ldg(&node_idx[e]);
        // Row gather: lane l reads float4 at dim 4*l of row n (coalesced 512B).
        float4 v = __ldg(&t4[(long long)n * FEAT4 + lane]);

        if (s != cur) {
            // Flush finished segment. Atomic because chunk-boundary segments
            // can be shared by two warps; interior segments hit distinct addrs.
            float* o = out + (long long)cur * FEAT + lane * 4;
            atomicAdd(o + 0, acc.x);
            atomicAdd(o + 1, acc.y);
            atomicAdd(o + 2, acc.z);
            atomicAdd(o + 3, acc.w);
            if (lane == 0) atomicAdd(&g_counts[cur], cnt);
            acc = make_float4(0.f, 0.f, 0.f, 0.f);
            cnt = 0.f;
            cur = s;
        }
        acc.x += v.x; acc.y += v.y; acc.z += v.z; acc.w += v.w;
        cnt += 1.f;
    }
    // Final flush.
    float* o = out + (long long)cur * FEAT + lane * 4;
    atomicAdd(o + 0, acc.x);
    atomicAdd(o + 1, acc.y);
    atomicAdd(o + 2, acc.z);
    atomicAdd(o + 3, acc.w);
    if (lane == 0) atomicAdd(&g_counts[cur], cnt);
}

__global__ void div_kernel(float* __restrict__ out, int H) {
    int i = blockIdx.x * blockDim.x + threadIdx.x;   // one float4 per thread
    int total = H * FEAT4;
    if (i >= total) return;
    int h = i >> 5;                                  // FEAT4 == 32
    float c = g_counts[h];
    float inv = 1.f / fmaxf(c, 1.f);
    float4 v = reinterpret_cast<float4*>(out)[i];
    v.x *= inv; v.y *= inv; v.z *= inv; v.w *= inv;
    reinterpret_cast<float4*>(out)[i] = v;
}

extern "C" void kernel_launch(void* const* d_in, const int* in_sizes, int n_in,
                              void* d_out, int out_size) {
    const float* table    = (const float*)d_in[0];
    const int*   node_idx = (const int*)d_in[1];
    const int*   seg_ids  = (const int*)d_in[2];
    float*       out      = (float*)d_out;

    int E = in_sizes[1];
    int H = out_size / FEAT;

    // 1) zero output + counts scratch
    {
        int out_vec4 = out_size / 4;
        zero_kernel<<<2048, 256>>>(out, out_vec4, H);
    }
    // 2) segment-sum accumulate
    {
        int warps = (E + CHUNK - 1) / CHUNK;
        int blocks = (warps * 32 + AGG_BLOCK - 1) / AGG_BLOCK;
        agg_kernel<<<blocks, AGG_BLOCK>>>(table, node_idx, seg_ids, out, E);
    }
    // 3) divide by counts -> mean
    {
        int total = H * FEAT4;
        div_kernel<<<(total + 255) / 256, 256>>>(out, H);
    }
}

// round 5
// speedup vs baseline: 1.1248x; 1.1248x over previous
#include <cuda_runtime.h>
#include <cuda_bf16.h>

// HyperedgeMeanAggregator: out[h, :] = mean over entries e with seg_ids[e]==h of
// embed_table[node_idx[e], :].  seg_ids is SORTED. Indices are int32 (JAX x64 off).
//
// Inputs: d_in[0]=embed_table f32[200000*128], d_in[1]=node_idx i32[E],
//         d_in[2]=seg_ids i32[E] (sorted), d_in[3]=num_hyperedges (unused).
// Output: f32 [H*128].

#define FEAT 128
#define FEAT4 (FEAT / 4)          // 32 float4 per row -> one warp covers a row
#define CHUNK 128                 // entries per warp (E=1.6M is a multiple of 128)
#define AGG_BLOCK 256             // 8 warps per block
#define MAX_H 65536

__device__ float g_counts[MAX_H];

__device__ __forceinline__ void red_v4(float* addr, float4 v) {
    asm volatile("red.global.add.v4.f32 [%0], {%1, %2, %3, %4};"
                 :: "l"(addr), "f"(v.x), "f"(v.y), "f"(v.z), "f"(v.w)
                 : "memory");
}

__global__ void agg_kernel(const float* __restrict__ table,
                           const int* __restrict__ node_idx,
                           const int* __restrict__ seg_ids,
                           float* __restrict__ out,
                           int E) {
    int gwarp = (blockIdx.x * blockDim.x + threadIdx.x) >> 5;
    int lane  = threadIdx.x & 31;

    int start = gwarp * CHUNK;
    if (start >= E) return;
    int end = start + CHUNK;
    if (end > E) end = E;

    const float4* t4 = reinterpret_cast<const float4*>(table);

    float4 acc = make_float4(0.f, 0.f, 0.f, 0.f);
    float  cnt = 0.f;
    int cur = __ldg(&seg_ids[start]);

#define PROC(S, V)                                                   \
    do {                                                             \
        if ((S) != cur) {                                            \
            red_v4(out + (long long)cur * FEAT + lane * 4, acc);     \
            if (lane == 0) atomicAdd(&g_counts[cur], cnt);           \
            acc = make_float4(0.f, 0.f, 0.f, 0.f);                   \
            cnt = 0.f;                                               \
            cur = (S);                                               \
        }                                                            \
        acc.x += (V).x; acc.y += (V).y;                              \
        acc.z += (V).z; acc.w += (V).w;                              \
        cnt += 1.f;                                                  \
    } while (0)

    int e = start;
    // start is a multiple of 128, so int4 loads are 16B-aligned.
    for (; e + 4 <= end; e += 4) {
        int4 s4 = *reinterpret_cast<const int4*>(&seg_ids[e]);   // uniform bcast
        int4 n4 = *reinterpret_cast<const int4*>(&node_idx[e]);  // uniform bcast
        // Issue all 4 row gathers before any consumption -> MLP=4.
        float4 v0 = __ldg(&t4[(long long)n4.x * FEAT4 + lane]);
        float4 v1 = __ldg(&t4[(long long)n4.y * FEAT4 + lane]);
        float4 v2 = __ldg(&t4[(long long)n4.z * FEAT4 + lane]);
        float4 v3 = __ldg(&t4[(long long)n4.w * FEAT4 + lane]);
        PROC(s4.x, v0);
        PROC(s4.y, v1);
        PROC(s4.z, v2);
        PROC(s4.w, v3);
    }
    for (; e < end; ++e) {   // generic tail (unused for E % 128 == 0)
        int s = __ldg(&seg_ids[e]);
        int n = __ldg(&node_idx[e]);
        float4 v = __ldg(&t4[(long long)n * FEAT4 + lane]);
        PROC(s, v);
    }
#undef PROC

    // Final flush.
    red_v4(out + (long long)cur * FEAT + lane * 4, acc);
    if (lane == 0) atomicAdd(&g_counts[cur], cnt);
}

__global__ void div_kernel(float* __restrict__ out, int H) {
    int i = blockIdx.x * blockDim.x + threadIdx.x;   // one float4 per thread
    int total = H * FEAT4;
    if (i >= total) return;
    int h = i >> 5;                                  // FEAT4 == 32
    float c = g_counts[h];
    float inv = 1.f / fmaxf(c, 1.f);
    float4 v = reinterpret_cast<float4*>(out)[i];
    v.x *= inv; v.y *= inv; v.z *= inv; v.w *= inv;
    reinterpret_cast<float4*>(out)[i] = v;
}

extern "C" void kernel_launch(void* const* d_in, const int* in_sizes, int n_in,
                              void* d_out, int out_size) {
    const float* table    = (const float*)d_in[0];
    const int*   node_idx = (const int*)d_in[1];
    const int*   seg_ids  = (const int*)d_in[2];
    float*       out      = (float*)d_out;

    int E = in_sizes[1];
    int H = out_size / FEAT;

    // 1) zero output + counts scratch (memset = capturable, full write BW)
    cudaMemsetAsync(out, 0, (size_t)out_size * sizeof(float));
    void* counts_ptr = nullptr;
    cudaGetSymbolAddress(&counts_ptr, g_counts);
    cudaMemsetAsync(counts_ptr, 0, (size_t)H * sizeof(float));

    // 2) segment-sum accumulate
    {
        int warps = (E + CHUNK - 1) / CHUNK;
        int blocks = (warps * 32 + AGG_BLOCK - 1) / AGG_BLOCK;
        agg_kernel<<<blocks, AGG_BLOCK>>>(table, node_idx, seg_ids, out, E);
    }
    // 3) divide by counts -> mean
    {
        int total = H * FEAT4;
        div_kernel<<<(total + 255) / 256, 256>>>(out, H);
    }
}

// round 6
// speedup vs baseline: 1.1291x; 1.0039x over previous
#include <cuda_runtime.h>
#include <cuda_bf16.h>

// HyperedgeMeanAggregator: out[h, :] = mean over entries e with seg_ids[e]==h of
// embed_table[node_idx[e], :].  seg_ids is SORTED. Indices are int32 (JAX x64 off).
//
// Inputs: d_in[0]=embed_table f32[200000*128], d_in[1]=node_idx i32[E],
//         d_in[2]=seg_ids i32[E] (sorted), d_in[3]=num_hyperedges (unused).
// Output: f32 [H*128].
//
// Strategy: (1) memset out+counts, (2) count entries per segment (run-compressed
// atomics over sorted seg_ids), (3) single gather pass that atomically reduces
// acc * (1/count) into out -> output IS the mean, no divide pass.

#define FEAT 128
#define FEAT4 (FEAT / 4)          // 32 float4 per row -> one warp covers a row
#define CHUNK 128                 // entries per warp (E multiple of 128)
#define AGG_BLOCK 256             // 8 warps per block
#define MAX_H 65536

__device__ int g_counts[MAX_H];

__device__ __forceinline__ void red_v4(float* addr, float4 v) {
    asm volatile("red.global.add.v4.f32 [%0], {%1, %2, %3, %4};"
                 :: "l"(addr), "f"(v.x), "f"(v.y), "f"(v.z), "f"(v.w)
                 : "memory");
}

// Count entries per segment. seg_ids sorted -> compress equal runs inside each
// int4 quad to cut atomic count ~4x (avg run length is 32).
__global__ void count_kernel(const int* __restrict__ seg_ids, int E4) {
    int stride = gridDim.x * blockDim.x;
    for (int i = blockIdx.x * blockDim.x + threadIdx.x; i < E4; i += stride) {
        int4 s4 = reinterpret_cast<const int4*>(seg_ids)[i];
        if (s4.x == s4.w) {
            atomicAdd(&g_counts[s4.x], 4);
        } else {
            int cur = s4.x, c = 1;
            int v[3] = {s4.y, s4.z, s4.w};
            #pragma unroll
            for (int k = 0; k < 3; ++k) {
                if (v[k] == cur) { c++; }
                else { atomicAdd(&g_counts[cur], c); cur = v[k]; c = 1; }
            }
            atomicAdd(&g_counts[cur], c);
        }
    }
}

__global__ void agg_kernel(const float* __restrict__ table,
                           const int* __restrict__ node_idx,
                           const int* __restrict__ seg_ids,
                           float* __restrict__ out,
                           int E) {
    int gwarp = (blockIdx.x * blockDim.x + threadIdx.x) >> 5;
    int lane  = threadIdx.x & 31;

    int start = gwarp * CHUNK;
    if (start >= E) return;
    int end = start + CHUNK;
    if (end > E) end = E;

    const float4* t4 = reinterpret_cast<const float4*>(table);

    float4 acc = make_float4(0.f, 0.f, 0.f, 0.f);
    int cur = __ldg(&seg_ids[start]);

#define FLUSH(SEG)                                                     \
    do {                                                               \
        float inv = 1.0f / (float)__ldg(&g_counts[SEG]);               \
        float4 m = make_float4(acc.x * inv, acc.y * inv,               \
                               acc.z * inv, acc.w * inv);              \
        red_v4(out + (long long)(SEG) * FEAT + lane * 4, m);           \
    } while (0)

#define PROC(S, V)                                                     \
    do {                                                               \
        if ((S) != cur) {                                              \
            FLUSH(cur);                                                \
            acc = make_float4(0.f, 0.f, 0.f, 0.f);                     \
            cur = (S);                                                 \
        }                                                              \
        acc.x += (V).x; acc.y += (V).y;                                \
        acc.z += (V).z; acc.w += (V).w;                                \
    } while (0)

    int e = start;
    // start is a multiple of 128, so int4 loads are 16B-aligned.
    for (; e + 4 <= end; e += 4) {
        int4 s4 = *reinterpret_cast<const int4*>(&seg_ids[e]);   // uniform bcast
        int4 n4 = *reinterpret_cast<const int4*>(&node_idx[e]);  // uniform bcast
        // Issue all 4 row gathers before consumption -> MLP=4.
        float4 v0 = __ldg(&t4[(long long)n4.x * FEAT4 + lane]);
        float4 v1 = __ldg(&t4[(long long)n4.y * FEAT4 + lane]);
        float4 v2 = __ldg(&t4[(long long)n4.z * FEAT4 + lane]);
        float4 v3 = __ldg(&t4[(long long)n4.w * FEAT4 + lane]);
        PROC(s4.x, v0);
        PROC(s4.y, v1);
        PROC(s4.z, v2);
        PROC(s4.w, v3);
    }
    for (; e < end; ++e) {   // generic tail (unused for E % 128 == 0)
        int s = __ldg(&seg_ids[e]);
        int n = __ldg(&node_idx[e]);
        float4 v = __ldg(&t4[(long long)n * FEAT4 + lane]);
        PROC(s, v);
    }
#undef PROC

    FLUSH(cur);   // final flush
#undef FLUSH
}

extern "C" void kernel_launch(void* const* d_in, const int* in_sizes, int n_in,
                              void* d_out, int out_size) {
    const float* table    = (const float*)d_in[0];
    const int*   node_idx = (const int*)d_in[1];
    const int*   seg_ids  = (const int*)d_in[2];
    float*       out      = (float*)d_out;

    int E = in_sizes[1];
    int H = out_size / FEAT;

    // 1) zero output (empty segments stay 0 = reference) + counts scratch
    cudaMemsetAsync(out, 0, (size_t)out_size * sizeof(float));
    void* counts_ptr = nullptr;
    cudaGetSymbolAddress(&counts_ptr, g_counts);
    cudaMemsetAsync(counts_ptr, 0, (size_t)H * sizeof(int));

    // 2) per-segment entry counts
    {
        int E4 = E / 4;   // E is a multiple of 4 here; tail handled below if not
        count_kernel<<<1024, 256>>>(seg_ids, E4);
    }

    // 3) gather + segment-mean accumulate (atomic adds of acc/count)
    {
        int warps = (E + CHUNK - 1) / CHUNK;
        int blocks = (warps * 32 + AGG_BLOCK - 1) / AGG_BLOCK;
        agg_kernel<<<blocks, AGG_BLOCK>>>(table, node_idx, seg_ids, out, E);
    }
}

// round 8
// speedup vs baseline: 1.1585x; 1.0260x over previous
#include <cuda_runtime.h>
#include <cuda_bf16.h>

// HyperedgeMeanAggregator: out[h,:] = mean_{e: seg_ids[e]==h} embed_table[node_idx[e],:]
// seg_ids SORTED, indices int32 (JAX x64 off).
//
// Segment-ownership design: warp w owns hyperedges [4w, 4w+4). Two binary
// searches over sorted seg_ids give its exact entry range; every segment is
// wholly owned by one warp -> plain STG writes (no atomics, no memset, no
// count pass). Lane l holds dims [4l, 4l+4) of the 128-dim accumulator.

#define FEAT   128
#define FEAT4  (FEAT / 4)     // 32 float4 per row = one warp
#define SEGW   4              // segments per warp
#define BLOCK  256            // 8 warps per block

__device__ __forceinline__ int lbound(const int* __restrict__ a, int n, int key) {
    int lo = 0, hi = n;
    while (lo < hi) {
        int mid = (lo + hi) >> 1;
        if (__ldg(&a[mid]) < key) lo = mid + 1; else hi = mid;
    }
    return lo;
}

__global__ __launch_bounds__(BLOCK)
void agg_kernel(const float* __restrict__ table,
                const int* __restrict__ node_idx,
                const int* __restrict__ seg_ids,
                float* __restrict__ out,
                int E, int H) {
    int gwarp = (blockIdx.x * blockDim.x + threadIdx.x) >> 5;
    int lane  = threadIdx.x & 31;

    int h_lo = gwarp * SEGW;
    if (h_lo >= H) return;
    int h_hi = h_lo + SEGW; if (h_hi > H) h_hi = H;

    // Entry range owned by this warp (all lanes compute identically).
    int eb = lbound(seg_ids, E, h_lo);
    int ee = lbound(seg_ids, E, h_hi);

    const float4* t4 = reinterpret_cast<const float4*>(table);
    float4* o4 = reinterpret_cast<float4*>(out);
    const float4 zero = make_float4(0.f, 0.f, 0.f, 0.f);

    float4 acc = zero;
    float  cnt = 0.f;
    int prev = h_lo - 1;          // last h written
    int cur  = (eb < ee) ? __ldg(&seg_ids[eb]) : -1;

#define FLUSH()                                                        \
    do {                                                               \
        for (int h = prev + 1; h < cur; ++h)  /* empty segs: zeros */  \
            o4[(unsigned)h * FEAT4 + lane] = zero;                     \
        float inv = 1.0f / cnt;                                        \
        float4 m = make_float4(acc.x * inv, acc.y * inv,               \
                               acc.z * inv, acc.w * inv);              \
        o4[(unsigned)cur * FEAT4 + lane] = m;                          \
        prev = cur;                                                    \
    } while (0)

#define PROC(S, V)                                                    \
    do {                                                              \
        if ((S) != cur) { FLUSH(); acc = zero; cnt = 0.f; cur = (S); }\
        acc.x += (V).x; acc.y += (V).y;                               \
        acc.z += (V).z; acc.w += (V).w;                               \
        cnt += 1.f;                                                   \
    } while (0)

    int e = eb;
    for (; e + 8 <= ee; e += 8) {
        int s0 = __ldg(&seg_ids[e + 0]), s1 = __ldg(&seg_ids[e + 1]);
        int s2 = __ldg(&seg_ids[e + 2]), s3 = __ldg(&seg_ids[e + 3]);
        int s4 = __ldg(&seg_ids[e + 4]), s5 = __ldg(&seg_ids[e + 5]);
        int s6 = __ldg(&seg_ids[e + 6]), s7 = __ldg(&seg_ids[e + 7]);
        unsigned n0 = (unsigned)__ldg(&node_idx[e + 0]) * FEAT4 + lane;
        unsigned n1 = (unsigned)__ldg(&node_idx[e + 1]) * FEAT4 + lane;
        unsigned n2 = (unsigned)__ldg(&node_idx[e + 2]) * FEAT4 + lane;
        unsigned n3 = (unsigned)__ldg(&node_idx[e + 3]) * FEAT4 + lane;
        unsigned n4 = (unsigned)__ldg(&node_idx[e + 4]) * FEAT4 + lane;
        unsigned n5 = (unsigned)__ldg(&node_idx[e + 5]) * FEAT4 + lane;
        unsigned n6 = (unsigned)__ldg(&node_idx[e + 6]) * FEAT4 + lane;
        unsigned n7 = (unsigned)__ldg(&node_idx[e + 7]) * FEAT4 + lane;
        // Issue all 8 row gathers before any consumption -> MLP=8.
        float4 v0 = __ldg(&t4[n0]);
        float4 v1 = __ldg(&t4[n1]);
        float4 v2 = __ldg(&t4[n2]);
        float4 v3 = __ldg(&t4[n3]);
        float4 v4 = __ldg(&t4[n4]);
        float4 v5 = __ldg(&t4[n5]);
        float4 v6 = __ldg(&t4[n6]);
        float4 v7 = __ldg(&t4[n7]);
        PROC(s0, v0); PROC(s1, v1); PROC(s2, v2); PROC(s3, v3);
        PROC(s4, v4); PROC(s5, v5); PROC(s6, v6); PROC(s7, v7);
    }
    for (; e < ee; ++e) {
        int s = __ldg(&seg_ids[e]);
        unsigned n = (unsigned)__ldg(&node_idx[e]) * FEAT4 + lane;
        float4 v = __ldg(&t4[n]);
        PROC(s, v);
    }

    if (cur >= 0) FLUSH();
    for (int h = prev + 1; h < h_hi; ++h)   // trailing empty segments
        o4[(unsigned)h * FEAT4 + lane] = zero;

#undef PROC
#undef FLUSH
}

extern "C" void kernel_launch(void* const* d_in, const int* in_sizes, int n_in,
                              void* d_out, int out_size) {
    const float* table    = (const float*)d_in[0];
    const int*   node_idx = (const int*)d_in[1];
    const int*   seg_ids  = (const int*)d_in[2];
    float*       out      = (float*)d_out;

    int E = in_sizes[1];
    int H = out_size / FEAT;

    int warps  = (H + SEGW - 1) / SEGW;
    int blocks = (warps * 32 + BLOCK - 1) / BLOCK;
    agg_kernel<<<blocks, BLOCK>>>(table, node_idx, seg_ids, out, E, H);
}